// round 9
// baseline (speedup 1.0000x reference)
#include <cuda_runtime.h>
#include <cuda_fp16.h>
#include <math.h>

#define NN 100000
#define EE 1600000
#define CSRCAP (EE + 3 * NN)

// ---------------- static device scratch ----------------
__device__ float g_bufA[NN * 64 + 64];  // GEMM out as __half (+dummy zero row n)
__device__ float g_bufB[NN * 64];       // agg out as __half (layers 1,2)
__device__ int   g_csrbuf[CSRCAP];      // padded CSR (row starts 4-aligned)
__device__ int   g_rowptr[NN + 1];
__device__ int   g_next[NN];
__device__ int   g_counts[NN];
__device__ float g_dinv[NN];
__device__ float g_stat[4 * 64];        // [sum1, sq1, sum2, sq2]
__device__ int   g_bsum[1024];
__device__ int   g_boff[1024];

// ---------------- packed f32x2 helpers ----------------
__device__ __forceinline__ unsigned long long pack2(float x, float y) {
    unsigned long long r;
    asm("mov.b64 %0, {%1, %2};" : "=l"(r) : "f"(x), "f"(y));
    return r;
}
__device__ __forceinline__ unsigned long long pack2s(float x) {
    unsigned long long r;
    asm("mov.b64 %0, {%1, %1};" : "=l"(r) : "f"(x));
    return r;
}
__device__ __forceinline__ void unpack2(unsigned long long v, float& x, float& y) {
    asm("mov.b64 {%0, %1}, %2;" : "=f"(x), "=f"(y) : "l"(v));
}
__device__ __forceinline__ void ffma2(unsigned long long& a, unsigned long long x,
                                      unsigned long long w) {
#if defined(__CUDA_ARCH__) && (__CUDA_ARCH__ >= 1000)
    asm("fma.rn.f32x2 %0, %1, %2, %0;" : "+l"(a) : "l"(x), "l"(w));
#else
    float ax, ay, xx, xy, wx, wy;
    unpack2(a, ax, ay); unpack2(x, xx, xy); unpack2(w, wx, wy);
    a = pack2(fmaf(xx, wx, ax), fmaf(xy, wy, ay));
#endif
}

// ---------------- zero counts + BN stats + dummy row ----------------
__global__ void zero_kernel(int* counts, float* stat, __half2* dummy, int n) {
    int i = blockIdx.x * blockDim.x + threadIdx.x;
    if (i < n) counts[i] = 0;
    if (i < 4 * 64) stat[i] = 0.0f;
    if (i < 32) dummy[i] = __floats2half2_rn(0.f, 0.f);
}

// ---------------- count in-degree (4 edges/thread, int4 loads) ----------------
__global__ void count_kernel(const int* __restrict__ dst, int* counts, int e) {
    int i = (blockIdx.x * blockDim.x + threadIdx.x) * 4;
    if (i + 4 <= e) {
        int4 d = *reinterpret_cast<const int4*>(&dst[i]);
        atomicAdd(&counts[d.x], 1);
        atomicAdd(&counts[d.y], 1);
        atomicAdd(&counts[d.z], 1);
        atomicAdd(&counts[d.w], 1);
    } else {
        for (; i < e; i++) atomicAdd(&counts[dst[i]], 1);
    }
}

// ---------------- two-level scan over PADDED counts ((c+3)&~3) ----------------
__global__ void bsum_kernel(const int* __restrict__ counts, int* bsum, int n) {
    __shared__ int sh[8];
    int base = blockIdx.x * 1024;
    int t = threadIdx.x;
    int s = 0;
    #pragma unroll
    for (int j = 0; j < 4; j++) {
        int i = base + t + j * 256;
        if (i < n) s += (counts[i] + 3) & ~3;
    }
    #pragma unroll
    for (int o = 16; o > 0; o >>= 1) s += __shfl_xor_sync(0xFFFFFFFFu, s, o);
    if ((t & 31) == 0) sh[t >> 5] = s;
    __syncthreads();
    if (t == 0) {
        int tot = 0;
        #pragma unroll
        for (int w = 0; w < 8; w++) tot += sh[w];
        bsum[blockIdx.x] = tot;
    }
}

__global__ void bscan_kernel(const int* __restrict__ bsum, int* boff, int* rowptr,
                             int nb, int n) {
    __shared__ int sh[4];
    __shared__ int carry_s;
    int t = threadIdx.x;
    if (t == 0) carry_s = 0;
    __syncthreads();
    for (int base = 0; base < nb; base += 128) {
        int i = base + t;
        int v = (i < nb) ? bsum[i] : 0;
        int incl = v;
        #pragma unroll
        for (int o = 1; o < 32; o <<= 1) {
            int u = __shfl_up_sync(0xFFFFFFFFu, incl, o);
            if ((t & 31) >= o) incl += u;
        }
        if ((t & 31) == 31) sh[t >> 5] = incl;
        __syncthreads();
        int wadd = 0;
        for (int w = 0; w < (t >> 5); w++) wadd += sh[w];
        int c = carry_s;
        if (i < nb) boff[i] = c + wadd + incl - v;
        __syncthreads();
        if (t == 127) carry_s = c + wadd + incl;
        __syncthreads();
    }
    if (t == 0) rowptr[n] = carry_s;   // padded total
}

// ---- scatter-scan (padded) -> rowptr, nextp, dinv; writes CSR padding --------
__global__ void scatter_scan_kernel(const int* __restrict__ counts,
                                    const int* __restrict__ boff,
                                    int* rowptr, int* nextp, float* dinv,
                                    int* csr, int n) {
    __shared__ int sh[8];
    int t = threadIdx.x;
    int i0 = blockIdx.x * 1024 + t * 4;
    int c[4] = {0, 0, 0, 0};
    #pragma unroll
    for (int q = 0; q < 4; q++)
        if (i0 + q < n) c[q] = counts[i0 + q];
    int cp[4];
    #pragma unroll
    for (int q = 0; q < 4; q++) cp[q] = (c[q] + 3) & ~3;
    int tot = cp[0] + cp[1] + cp[2] + cp[3];
    int incl = tot;
    #pragma unroll
    for (int o = 1; o < 32; o <<= 1) {
        int u = __shfl_up_sync(0xFFFFFFFFu, incl, o);
        if ((t & 31) >= o) incl += u;
    }
    if ((t & 31) == 31) sh[t >> 5] = incl;
    __syncthreads();
    int wadd = 0;
    for (int w = 0; w < (t >> 5); w++) wadd += sh[w];
    int off = boff[blockIdx.x] + wadd + incl - tot;
    #pragma unroll
    for (int q = 0; q < 4; q++) {
        int i = i0 + q;
        if (i < n) {
            rowptr[i] = off;
            nextp[i]  = off;
            dinv[i]   = rsqrtf((float)(c[q] + 1));
            for (int d = c[q]; d < cp[q]; d++)   // padding -> dummy zero row
                csr[off + d] = n;
        }
        off += cp[q];
    }
}

// ---------------- fill CSR (4 edges/thread) ----------------
__global__ void fill_kernel(const int* __restrict__ src, const int* __restrict__ dst,
                            int* nextp, int* csr, int e) {
    int i = (blockIdx.x * blockDim.x + threadIdx.x) * 4;
    if (i + 4 <= e) {
        int4 d = *reinterpret_cast<const int4*>(&dst[i]);
        int4 s = *reinterpret_cast<const int4*>(&src[i]);
        csr[atomicAdd(&nextp[d.x], 1)] = s.x;
        csr[atomicAdd(&nextp[d.y], 1)] = s.y;
        csr[atomicAdd(&nextp[d.z], 1)] = s.z;
        csr[atomicAdd(&nextp[d.w], 1)] = s.w;
    } else {
        for (; i < e; i++) {
            int p = atomicAdd(&nextp[dst[i]], 1);
            csr[p] = src[i];
        }
    }
}

// ---------------- GEMM layer 1: register-resident X ----------------
// 64-row tiles; lane owns rows lane, lane+32 streamed through registers in
// four k=32 chunks (per-lane-contiguous 128B loads). Only W in smem (32KB
// static) -> 6 blocks/SM, no __syncthreads in the tile loop.
__global__ __launch_bounds__(256, 6)
void gemm1_kernel(const float* __restrict__ X, const float* __restrict__ W,
                  const float* __restrict__ bias,
                  __half* __restrict__ Yh, int n, int ntiles) {
    constexpr int CIN = 128;
    __shared__ float Wsm[CIN * 64];
    int t = threadIdx.x, w = t >> 5, lane = t & 31;

    for (int idx = t; idx < CIN * 64; idx += 256) {
        int o = idx & 63, k = idx >> 6;
        Wsm[k * 64 + o] = __ldg(&W[o * CIN + k]);
    }
    __syncthreads();

    const float2* b2 = reinterpret_cast<const float2*>(bias);
    for (int tile = blockIdx.x; tile < ntiles; tile += gridDim.x) {
        int row0 = tile * 64;
        int g0 = row0 + lane, g1 = g0 + 32;
        const float4* x0p = reinterpret_cast<const float4*>(X + (size_t)g0 * CIN);
        const float4* x1p = reinterpret_cast<const float4*>(X + (size_t)g1 * CIN);
        bool v0 = g0 < n, v1 = g1 < n;

        unsigned long long acc0[4], acc1[4];
        #pragma unroll
        for (int p = 0; p < 4; p++) {
            float2 bp = __ldg(&b2[w * 4 + p]);
            acc0[p] = pack2(bp.x, bp.y);
            acc1[p] = acc0[p];
        }

        #pragma unroll
        for (int c = 0; c < 4; c++) {
            float4 xr0[8], xr1[8];
            const float4 z4 = make_float4(0.f, 0.f, 0.f, 0.f);
            #pragma unroll
            for (int j = 0; j < 8; j++) xr0[j] = v0 ? __ldg(&x0p[c * 8 + j]) : z4;
            #pragma unroll
            for (int j = 0; j < 8; j++) xr1[j] = v1 ? __ldg(&x1p[c * 8 + j]) : z4;
            #pragma unroll
            for (int j = 0; j < 8; j++) {
                #pragma unroll
                for (int kk = 0; kk < 4; kk++) {
                    int k = c * 32 + j * 4 + kk;
                    const ulonglong2* wp =
                        reinterpret_cast<const ulonglong2*>(&Wsm[k * 64 + w * 8]);
                    ulonglong2 wv0 = wp[0];
                    ulonglong2 wv1 = wp[1];
                    unsigned long long pa = pack2s((&xr0[j].x)[kk]);
                    unsigned long long pb = pack2s((&xr1[j].x)[kk]);
                    ffma2(acc0[0], pa, wv0.x); ffma2(acc0[1], pa, wv0.y);
                    ffma2(acc0[2], pa, wv1.x); ffma2(acc0[3], pa, wv1.y);
                    ffma2(acc1[0], pb, wv0.x); ffma2(acc1[1], pb, wv0.y);
                    ffma2(acc1[2], pb, wv1.x); ffma2(acc1[3], pb, wv1.y);
                }
            }
        }

        if (v0) {
            float a, b;
            __half2 hp[4];
            unpack2(acc0[0], a, b); hp[0] = __floats2half2_rn(a, b);
            unpack2(acc0[1], a, b); hp[1] = __floats2half2_rn(a, b);
            unpack2(acc0[2], a, b); hp[2] = __floats2half2_rn(a, b);
            unpack2(acc0[3], a, b); hp[3] = __floats2half2_rn(a, b);
            *reinterpret_cast<uint4*>(&Yh[(size_t)g0 * 64 + w * 8]) =
                *reinterpret_cast<const uint4*>(hp);
        }
        if (v1) {
            float a, b;
            __half2 hp[4];
            unpack2(acc1[0], a, b); hp[0] = __floats2half2_rn(a, b);
            unpack2(acc1[1], a, b); hp[1] = __floats2half2_rn(a, b);
            unpack2(acc1[2], a, b); hp[2] = __floats2half2_rn(a, b);
            unpack2(acc1[3], a, b); hp[3] = __floats2half2_rn(a, b);
            *reinterpret_cast<uint4*>(&Yh[(size_t)g1 * 64 + w * 8]) =
                *reinterpret_cast<const uint4*>(hp);
        }
    }
}

// ---------------- prescale bufA by dinv (fp32 math, one fp16 rounding) --------
__global__ void scale_kernel(uint4* __restrict__ Y, const float* __restrict__ dinv,
                             int n) {
    int tid = blockIdx.x * blockDim.x + threadIdx.x;   // one uint4 = 8 halves
    if (tid >= n * 8) return;
    float d = __ldg(&dinv[tid >> 3]);
    uint4 v = Y[tid];
    __half2* h = reinterpret_cast<__half2*>(&v);
    #pragma unroll
    for (int q = 0; q < 4; q++) {
        float2 f = __half22float2(h[q]);
        h[q] = __floats2half2_rn(f.x * d, f.y * d);
    }
    Y[tid] = v;
}

// ---------------- aggregation (prescaled messages, 16-deep MLP) --------------
// out_i = dinv_i * (Y'_i + sum_{p} Y'_{csr[p]}); padding rows point at zero row n.
template <bool LOGSM, bool STATS>
__global__ __launch_bounds__(256)
void agg_kernel(const __half2* __restrict__ Yh,
                const int* __restrict__ rowptr, const int* __restrict__ csr,
                const float* __restrict__ dinv,
                __half2* __restrict__ outh, float2* __restrict__ outf,
                float* __restrict__ stats, int n) {
    int lane = threadIdx.x & 31;
    int wid  = (blockIdx.x * blockDim.x + threadIdx.x) >> 5;
    int nw   = (gridDim.x * blockDim.x) >> 5;
    float s0 = 0.f, q0 = 0.f, s1 = 0.f, q1 = 0.f;

    for (int i = wid; i < n; i += nw) {
        float di = __ldg(&dinv[i]);
        float2 a = __half22float2(__ldg(&Yh[i * 32 + lane]));
        int p = __ldg(&rowptr[i]);
        int e = __ldg(&rowptr[i + 1]);
        for (; p + 16 <= e; p += 16) {
            int4 ja = *reinterpret_cast<const int4*>(&csr[p]);
            int4 jb = *reinterpret_cast<const int4*>(&csr[p + 4]);
            int4 jc = *reinterpret_cast<const int4*>(&csr[p + 8]);
            int4 jd = *reinterpret_cast<const int4*>(&csr[p + 12]);
            float2 v[16];
            v[0]  = __half22float2(__ldg(&Yh[ja.x * 32 + lane]));
            v[1]  = __half22float2(__ldg(&Yh[ja.y * 32 + lane]));
            v[2]  = __half22float2(__ldg(&Yh[ja.z * 32 + lane]));
            v[3]  = __half22float2(__ldg(&Yh[ja.w * 32 + lane]));
            v[4]  = __half22float2(__ldg(&Yh[jb.x * 32 + lane]));
            v[5]  = __half22float2(__ldg(&Yh[jb.y * 32 + lane]));
            v[6]  = __half22float2(__ldg(&Yh[jb.z * 32 + lane]));
            v[7]  = __half22float2(__ldg(&Yh[jb.w * 32 + lane]));
            v[8]  = __half22float2(__ldg(&Yh[jc.x * 32 + lane]));
            v[9]  = __half22float2(__ldg(&Yh[jc.y * 32 + lane]));
            v[10] = __half22float2(__ldg(&Yh[jc.z * 32 + lane]));
            v[11] = __half22float2(__ldg(&Yh[jc.w * 32 + lane]));
            v[12] = __half22float2(__ldg(&Yh[jd.x * 32 + lane]));
            v[13] = __half22float2(__ldg(&Yh[jd.y * 32 + lane]));
            v[14] = __half22float2(__ldg(&Yh[jd.z * 32 + lane]));
            v[15] = __half22float2(__ldg(&Yh[jd.w * 32 + lane]));
            #pragma unroll
            for (int q = 0; q < 16; q++) { a.x += v[q].x; a.y += v[q].y; }
        }
        if (p + 8 <= e) {
            int4 ja = *reinterpret_cast<const int4*>(&csr[p]);
            int4 jb = *reinterpret_cast<const int4*>(&csr[p + 4]);
            float2 v[8];
            v[0] = __half22float2(__ldg(&Yh[ja.x * 32 + lane]));
            v[1] = __half22float2(__ldg(&Yh[ja.y * 32 + lane]));
            v[2] = __half22float2(__ldg(&Yh[ja.z * 32 + lane]));
            v[3] = __half22float2(__ldg(&Yh[ja.w * 32 + lane]));
            v[4] = __half22float2(__ldg(&Yh[jb.x * 32 + lane]));
            v[5] = __half22float2(__ldg(&Yh[jb.y * 32 + lane]));
            v[6] = __half22float2(__ldg(&Yh[jb.z * 32 + lane]));
            v[7] = __half22float2(__ldg(&Yh[jb.w * 32 + lane]));
            #pragma unroll
            for (int q = 0; q < 8; q++) { a.x += v[q].x; a.y += v[q].y; }
            p += 8;
        }
        if (p < e) {
            int4 ja = *reinterpret_cast<const int4*>(&csr[p]);
            float2 v0 = __half22float2(__ldg(&Yh[ja.x * 32 + lane]));
            float2 v1 = __half22float2(__ldg(&Yh[ja.y * 32 + lane]));
            float2 v2 = __half22float2(__ldg(&Yh[ja.z * 32 + lane]));
            float2 v3 = __half22float2(__ldg(&Yh[ja.w * 32 + lane]));
            a.x += (v0.x + v1.x) + (v2.x + v3.x);
            a.y += (v0.y + v1.y) + (v2.y + v3.y);
        }
        a.x *= di;
        a.y *= di;
        if (STATS) {
            s0 += a.x; q0 = fmaf(a.x, a.x, q0);
            s1 += a.y; q1 = fmaf(a.y, a.y, q1);
        }
        if (!LOGSM) {
            outh[i * 32 + lane] = __floats2half2_rn(a.x, a.y);
        } else {
            float m = fmaxf(a.x, a.y);
            #pragma unroll
            for (int o = 16; o > 0; o >>= 1)
                m = fmaxf(m, __shfl_xor_sync(0xFFFFFFFFu, m, o));
            float sum = expf(a.x - m) + expf(a.y - m);
            #pragma unroll
            for (int o = 16; o > 0; o >>= 1)
                sum += __shfl_xor_sync(0xFFFFFFFFu, sum, o);
            float lz = m + logf(sum);
            outf[i * 32 + lane] = make_float2(a.x - lz, a.y - lz);
        }
    }

    if (STATS) {
        __shared__ float4 red[256];
        red[threadIdx.x] = make_float4(s0, q0, s1, q1);
        __syncthreads();
        if (threadIdx.x < 32) {
            float4 r = red[threadIdx.x];
            #pragma unroll
            for (int w = 1; w < 8; w++) {
                float4 o = red[w * 32 + threadIdx.x];
                r.x += o.x; r.y += o.y; r.z += o.z; r.w += o.w;
            }
            atomicAdd(&stats[2 * threadIdx.x],          r.x);
            atomicAdd(&stats[64 + 2 * threadIdx.x],     r.y);
            atomicAdd(&stats[2 * threadIdx.x + 1],      r.z);
            atomicAdd(&stats[64 + 2 * threadIdx.x + 1], r.w);
        }
    }
}

// ---------------- GEMM layers 2/3 (CIN=64, half in, BN+ReLU, dinv prescale) ----
__global__ __launch_bounds__(256)
void gemm2_kernel(const __half* __restrict__ X, const float* __restrict__ W,
                  const float* __restrict__ bias,
                  const float* __restrict__ stat, const float* __restrict__ gam,
                  const float* __restrict__ bet, float invn,
                  const float* __restrict__ dinv,
                  __half* __restrict__ Yh, int n, int ntiles) {
    constexpr int CIN = 64, XS = 68;
    extern __shared__ float sm[];
    float* Wsm = sm;
    float* Xsm = sm + CIN * 64;
    __shared__ float scl[64], shf[64];
    int t = threadIdx.x, w = t >> 5, lane = t & 31;

    if (t < 64) {
        float mean = stat[t] * invn;
        float var  = stat[64 + t] * invn - mean * mean;
        float sc   = rsqrtf(var + 1e-5f) * gam[t];
        scl[t] = sc;
        shf[t] = bet[t] - mean * sc;
    }
    for (int idx = t; idx < CIN * 64; idx += 256) {
        int o = idx & 63, k = idx >> 6;
        Wsm[k * 64 + o] = __ldg(&W[o * CIN + k]);
    }

    for (int tile = blockIdx.x; tile < ntiles; tile += gridDim.x) {
        __syncthreads();
        int row0 = tile * 128;
        for (int idx = t; idx < 128 * (CIN / 4); idx += 256) {
            int r  = idx >> 4;
            int c4 = idx & 15;
            int gr = row0 + r;
            float4 v = make_float4(0.f, 0.f, 0.f, 0.f);
            if (gr < n) {
                const __half2* xh = reinterpret_cast<const __half2*>(
                    X + (size_t)gr * CIN + c4 * 4);
                float2 p0 = __half22float2(xh[0]);
                float2 p1 = __half22float2(xh[1]);
                v = make_float4(p0.x, p0.y, p1.x, p1.y);
            }
            int c = c4 * 4;
            v.x = fmaxf(fmaf(v.x, scl[c],     shf[c]),     0.f);
            v.y = fmaxf(fmaf(v.y, scl[c + 1], shf[c + 1]), 0.f);
            v.z = fmaxf(fmaf(v.z, scl[c + 2], shf[c + 2]), 0.f);
            v.w = fmaxf(fmaf(v.w, scl[c + 3], shf[c + 3]), 0.f);
            *reinterpret_cast<float4*>(&Xsm[r * XS + c4 * 4]) = v;
        }
        __syncthreads();

        unsigned long long acc[4][4];
        const float2* b2 = reinterpret_cast<const float2*>(bias);
        #pragma unroll
        for (int p = 0; p < 4; p++) {
            float2 bp = __ldg(&b2[w * 4 + p]);
            unsigned long long bb = pack2(bp.x, bp.y);
            acc[0][p] = bb; acc[1][p] = bb; acc[2][p] = bb; acc[3][p] = bb;
        }
        #pragma unroll 2
        for (int k = 0; k < CIN; k += 4) {
            float4 xr[4];
            #pragma unroll
            for (int rr = 0; rr < 4; rr++)
                xr[rr] = *reinterpret_cast<const float4*>(&Xsm[(lane + rr * 32) * XS + k]);
            #pragma unroll
            for (int kk = 0; kk < 4; kk++) {
                const ulonglong2* wp =
                    reinterpret_cast<const ulonglong2*>(&Wsm[(k + kk) * 64 + w * 8]);
                ulonglong2 wv0 = wp[0];
                ulonglong2 wv1 = wp[1];
                #pragma unroll
                for (int rr = 0; rr < 4; rr++) {
                    unsigned long long pa = pack2s((&xr[rr].x)[kk]);
                    ffma2(acc[rr][0], pa, wv0.x); ffma2(acc[rr][1], pa, wv0.y);
                    ffma2(acc[rr][2], pa, wv1.x); ffma2(acc[rr][3], pa, wv1.y);
                }
            }
        }
        #pragma unroll
        for (int rr = 0; rr < 4; rr++) {
            int gr = row0 + lane + rr * 32;
            if (gr < n) {
                float di = __ldg(&dinv[gr]);
                float a, b;
                __half2 hp[4];
                unpack2(acc[rr][0], a, b); hp[0] = __floats2half2_rn(a * di, b * di);
                unpack2(acc[rr][1], a, b); hp[1] = __floats2half2_rn(a * di, b * di);
                unpack2(acc[rr][2], a, b); hp[2] = __floats2half2_rn(a * di, b * di);
                unpack2(acc[rr][3], a, b); hp[3] = __floats2half2_rn(a * di, b * di);
                *reinterpret_cast<uint4*>(&Yh[(size_t)gr * 64 + w * 8]) =
                    *reinterpret_cast<const uint4*>(hp);
            }
        }
    }
}

// ---------------- host launcher ----------------
extern "C" void kernel_launch(void* const* d_in, const int* in_sizes, int n_in,
                              void* d_out, int out_size) {
    const float* x   = (const float*)d_in[0];
    const int*   ei  = (const int*)  d_in[1];
    const float* W1  = (const float*)d_in[2];
    const float* b1  = (const float*)d_in[3];
    const float* ga1 = (const float*)d_in[4];
    const float* be1 = (const float*)d_in[5];
    const float* W2  = (const float*)d_in[6];
    const float* b2  = (const float*)d_in[7];
    const float* ga2 = (const float*)d_in[8];
    const float* be2 = (const float*)d_in[9];
    const float* W3  = (const float*)d_in[10];
    const float* b3  = (const float*)d_in[11];
    float* out = (float*)d_out;

    int N = in_sizes[0] / 128;
    int E = in_sizes[1] / 2;
    const int* src = ei;
    const int* dst = ei + E;

    void* p;
    cudaGetSymbolAddress(&p, g_bufA);   __half* bufA  = (__half*)p;
    cudaGetSymbolAddress(&p, g_bufB);   __half* bufB  = (__half*)p;
    cudaGetSymbolAddress(&p, g_csrbuf); int*   csr    = (int*)p;
    cudaGetSymbolAddress(&p, g_rowptr); int*   rowptr = (int*)p;
    cudaGetSymbolAddress(&p, g_next);   int*   nextp  = (int*)p;
    cudaGetSymbolAddress(&p, g_counts); int*   counts = (int*)p;
    cudaGetSymbolAddress(&p, g_dinv);   float* dinv   = (float*)p;
    cudaGetSymbolAddress(&p, g_stat);   float* stat   = (float*)p;
    cudaGetSymbolAddress(&p, g_bsum);   int*   bsum   = (int*)p;
    cudaGetSymbolAddress(&p, g_boff);   int*   boff   = (int*)p;

    static cudaStream_t sB = nullptr;
    static cudaEvent_t  evF = nullptr, evJ = nullptr;
    if (!sB) {
        cudaStreamCreateWithFlags(&sB, cudaStreamNonBlocking);
        cudaEventCreateWithFlags(&evF, cudaEventDisableTiming);
        cudaEventCreateWithFlags(&evJ, cudaEventDisableTiming);
    }

    const int SMEM2 = (64 * 64 + 128 * 68) * 4;        // 51200 B
    cudaFuncSetAttribute(gemm2_kernel,
                         cudaFuncAttributeMaxDynamicSharedMemorySize, SMEM2);

    int gridN   = (N + 255) / 256;
    int gridE4  = (E / 4 + 255) / 256;
    int nb      = (N + 1023) / 1024;
    int ntiles1 = (N + 63) / 64;
    int ntiles2 = (N + 127) / 128;
    const int G1   = 888;    // 6 blocks/SM (32KB static smem)
    const int G2   = 592;
    const int AGGB = 1184;
    int gridS = (N * 8 + 255) / 256;
    float invn = 1.0f / (float)N;

    const __half2* bufA2 = (const __half2*)bufA;
    __half2* bufB2  = (__half2*)bufB;
    __half2* dummy2 = (__half2*)bufA + (size_t)N * 32;
    float2*  out2   = (float2*)out;

    // ---- fork: CSR build chain on sB overlaps gemm1 (no dinv/csr dep) ----
    // Call order => launch idx: zero#1, count#2, bsum#3, gemm1#4 (profiled)
    cudaEventRecord(evF, 0);
    cudaStreamWaitEvent(sB, evF, 0);

    zero_kernel<<<gridN, 256, 0, sB>>>(counts, stat, dummy2, N);               // 1
    count_kernel<<<gridE4, 256, 0, sB>>>(dst, counts, E);                      // 2
    bsum_kernel<<<nb, 256, 0, sB>>>(counts, bsum, N);                          // 3
    gemm1_kernel<<<G1, 256>>>(x, W1, b1, bufA, N, ntiles1);                    // 4
    bscan_kernel<<<1, 128, 0, sB>>>(bsum, boff, rowptr, nb, N);                // 5
    scatter_scan_kernel<<<nb, 256, 0, sB>>>(counts, boff, rowptr, nextp, dinv,
                                            csr, N);                           // 6
    fill_kernel<<<gridE4, 256, 0, sB>>>(src, dst, nextp, csr, E);              // 7
    cudaEventRecord(evJ, sB);
    cudaStreamWaitEvent(0, evJ, 0);

    // prescale layer-1 messages by dinv, then uniform non-RAW aggs
    scale_kernel<<<gridS, 256>>>((uint4*)bufA, dinv, N);                       // 8
    agg_kernel<false, true><<<AGGB, 256>>>(
        bufA2, rowptr, csr, dinv, bufB2, nullptr, stat, N);                    // 9

    // layer 2
    gemm2_kernel<<<G2, 256, SMEM2>>>(bufB, W2, b2, stat, ga1, be1,
                                     invn, dinv, bufA, N, ntiles2);            // 10
    agg_kernel<false, true><<<AGGB, 256>>>(
        bufA2, rowptr, csr, dinv, bufB2, nullptr, stat + 128, N);              // 11

    // layer 3 + log_softmax
    gemm2_kernel<<<G2, 256, SMEM2>>>(bufB, W3, b3, stat + 128, ga2, be2,
                                     invn, dinv, bufA, N, ntiles2);            // 12
    agg_kernel<true, false><<<AGGB, 256>>>(
        bufA2, rowptr, csr, dinv, nullptr, out2, nullptr, N);                  // 13
}

// round 10
// speedup vs baseline: 1.5100x; 1.5100x over previous
#include <cuda_runtime.h>
#include <cuda_fp16.h>
#include <math.h>

#define NN 100000
#define EE 1600000
#define CSRCAP (EE + 3 * NN)

// ---------------- static device scratch ----------------
__device__ float g_bufA[NN * 64 + 64];  // GEMM out as __half (+dummy zero row n)
__device__ float g_bufB[NN * 64];       // agg out as __half (layers 1,2)
__device__ int   g_csrbuf[CSRCAP];      // padded CSR (row starts 4-aligned)
__device__ int   g_rowptr[NN + 1];
__device__ int   g_next[NN];
__device__ int   g_counts[NN];
__device__ float g_dinv[NN];
__device__ float g_stat[4 * 64];        // [sum1, sq1, sum2, sq2]
__device__ int   g_bsum[1024];
__device__ int   g_boff[1024];

// ---------------- packed f32x2 helpers ----------------
__device__ __forceinline__ unsigned long long pack2(float x, float y) {
    unsigned long long r;
    asm("mov.b64 %0, {%1, %2};" : "=l"(r) : "f"(x), "f"(y));
    return r;
}
__device__ __forceinline__ unsigned long long pack2s(float x) {
    unsigned long long r;
    asm("mov.b64 %0, {%1, %1};" : "=l"(r) : "f"(x));
    return r;
}
__device__ __forceinline__ void unpack2(unsigned long long v, float& x, float& y) {
    asm("mov.b64 {%0, %1}, %2;" : "=f"(x), "=f"(y) : "l"(v));
}
__device__ __forceinline__ void ffma2(unsigned long long& a, unsigned long long x,
                                      unsigned long long w) {
#if defined(__CUDA_ARCH__) && (__CUDA_ARCH__ >= 1000)
    asm("fma.rn.f32x2 %0, %1, %2, %0;" : "+l"(a) : "l"(x), "l"(w));
#else
    float ax, ay, xx, xy, wx, wy;
    unpack2(a, ax, ay); unpack2(x, xx, xy); unpack2(w, wx, wy);
    a = pack2(fmaf(xx, wx, ax), fmaf(xy, wy, ay));
#endif
}

// ---------------- zero counts + BN stats + dummy row ----------------
__global__ void zero_kernel(int* counts, float* stat, __half2* dummy, int n) {
    int i = blockIdx.x * blockDim.x + threadIdx.x;
    if (i < n) counts[i] = 0;
    if (i < 4 * 64) stat[i] = 0.0f;
    if (i < 32) dummy[i] = __floats2half2_rn(0.f, 0.f);
}

// ---------------- count in-degree (4 edges/thread, int4 loads) ----------------
__global__ void count_kernel(const int* __restrict__ dst, int* counts, int e) {
    int i = (blockIdx.x * blockDim.x + threadIdx.x) * 4;
    if (i + 4 <= e) {
        int4 d = *reinterpret_cast<const int4*>(&dst[i]);
        atomicAdd(&counts[d.x], 1);
        atomicAdd(&counts[d.y], 1);
        atomicAdd(&counts[d.z], 1);
        atomicAdd(&counts[d.w], 1);
    } else {
        for (; i < e; i++) atomicAdd(&counts[dst[i]], 1);
    }
}

// ---------------- two-level scan over PADDED counts ((c+3)&~3) ----------------
__global__ void bsum_kernel(const int* __restrict__ counts, int* bsum, int n) {
    __shared__ int sh[8];
    int base = blockIdx.x * 1024;
    int t = threadIdx.x;
    int s = 0;
    #pragma unroll
    for (int j = 0; j < 4; j++) {
        int i = base + t + j * 256;
        if (i < n) s += (counts[i] + 3) & ~3;
    }
    #pragma unroll
    for (int o = 16; o > 0; o >>= 1) s += __shfl_xor_sync(0xFFFFFFFFu, s, o);
    if ((t & 31) == 0) sh[t >> 5] = s;
    __syncthreads();
    if (t == 0) {
        int tot = 0;
        #pragma unroll
        for (int w = 0; w < 8; w++) tot += sh[w];
        bsum[blockIdx.x] = tot;
    }
}

__global__ void bscan_kernel(const int* __restrict__ bsum, int* boff, int* rowptr,
                             int nb, int n) {
    __shared__ int sh[4];
    __shared__ int carry_s;
    int t = threadIdx.x;
    if (t == 0) carry_s = 0;
    __syncthreads();
    for (int base = 0; base < nb; base += 128) {
        int i = base + t;
        int v = (i < nb) ? bsum[i] : 0;
        int incl = v;
        #pragma unroll
        for (int o = 1; o < 32; o <<= 1) {
            int u = __shfl_up_sync(0xFFFFFFFFu, incl, o);
            if ((t & 31) >= o) incl += u;
        }
        if ((t & 31) == 31) sh[t >> 5] = incl;
        __syncthreads();
        int wadd = 0;
        for (int w = 0; w < (t >> 5); w++) wadd += sh[w];
        int c = carry_s;
        if (i < nb) boff[i] = c + wadd + incl - v;
        __syncthreads();
        if (t == 127) carry_s = c + wadd + incl;
        __syncthreads();
    }
    if (t == 0) rowptr[n] = carry_s;   // padded total
}

// ---- scatter-scan (padded) -> rowptr, nextp, dinv; writes CSR padding --------
__global__ void scatter_scan_kernel(const int* __restrict__ counts,
                                    const int* __restrict__ boff,
                                    int* rowptr, int* nextp, float* dinv,
                                    int* csr, int n) {
    __shared__ int sh[8];
    int t = threadIdx.x;
    int i0 = blockIdx.x * 1024 + t * 4;
    int c[4] = {0, 0, 0, 0};
    #pragma unroll
    for (int q = 0; q < 4; q++)
        if (i0 + q < n) c[q] = counts[i0 + q];
    int cp[4];
    #pragma unroll
    for (int q = 0; q < 4; q++) cp[q] = (c[q] + 3) & ~3;
    int tot = cp[0] + cp[1] + cp[2] + cp[3];
    int incl = tot;
    #pragma unroll
    for (int o = 1; o < 32; o <<= 1) {
        int u = __shfl_up_sync(0xFFFFFFFFu, incl, o);
        if ((t & 31) >= o) incl += u;
    }
    if ((t & 31) == 31) sh[t >> 5] = incl;
    __syncthreads();
    int wadd = 0;
    for (int w = 0; w < (t >> 5); w++) wadd += sh[w];
    int off = boff[blockIdx.x] + wadd + incl - tot;
    #pragma unroll
    for (int q = 0; q < 4; q++) {
        int i = i0 + q;
        if (i < n) {
            rowptr[i] = off;
            nextp[i]  = off;
            dinv[i]   = rsqrtf((float)(c[q] + 1));
            for (int d = c[q]; d < cp[q]; d++)   // padding -> dummy zero row
                csr[off + d] = n;
        }
        off += cp[q];
    }
}

// ---------------- fill CSR (4 edges/thread) ----------------
__global__ void fill_kernel(const int* __restrict__ src, const int* __restrict__ dst,
                            int* nextp, int* csr, int e) {
    int i = (blockIdx.x * blockDim.x + threadIdx.x) * 4;
    if (i + 4 <= e) {
        int4 d = *reinterpret_cast<const int4*>(&dst[i]);
        int4 s = *reinterpret_cast<const int4*>(&src[i]);
        csr[atomicAdd(&nextp[d.x], 1)] = s.x;
        csr[atomicAdd(&nextp[d.y], 1)] = s.y;
        csr[atomicAdd(&nextp[d.z], 1)] = s.z;
        csr[atomicAdd(&nextp[d.w], 1)] = s.w;
    } else {
        for (; i < e; i++) {
            int p = atomicAdd(&nextp[dst[i]], 1);
            csr[p] = src[i];
        }
    }
}

// ---------------- GEMM layer 1 (CIN=128, fp32 in, raw half out) ----------------
// 64-row tiles, cp.async double-buffered X stage overlapping compute.
// (Known-good R8 config: regs=64, ~64us, runs concurrently with CSR chain.)
__global__ __launch_bounds__(256)
void gemm1_kernel(const float* __restrict__ X, const float* __restrict__ W,
                  const float* __restrict__ bias,
                  __half* __restrict__ Yh, int n, int ntiles) {
    constexpr int CIN = 128, XS = 132, ROWS = 64;
    extern __shared__ float sm[];
    float* Wsm = sm;
    float* Xb0 = sm + CIN * 64;
    float* Xb1 = Xb0 + ROWS * XS;
    int t = threadIdx.x, w = t >> 5, lane = t & 31;

    for (int idx = t; idx < CIN * 64; idx += 256) {
        int o = idx & 63, k = idx >> 6;
        Wsm[k * 64 + o] = __ldg(&W[o * CIN + k]);
    }

    auto stage = [&](int tile, float* dstbuf) {
        int row0 = tile * ROWS;
        #pragma unroll
        for (int j = 0; j < 8; j++) {
            int idx = t + j * 256;
            int r  = idx >> 5;
            int c4 = idx & 31;
            int gr = row0 + r;
            unsigned int daddr =
                (unsigned int)__cvta_generic_to_shared(&dstbuf[r * XS + c4 * 4]);
            const float* gp = X + (size_t)gr * CIN + c4 * 4;
            int sz = (gr < n) ? 16 : 0;
            asm volatile("cp.async.cg.shared.global [%0], [%1], 16, %2;"
                         :: "r"(daddr), "l"(gp), "r"(sz));
        }
        asm volatile("cp.async.commit_group;" ::: "memory");
    };

    int tile = blockIdx.x;
    if (tile < ntiles) stage(tile, Xb0);
    int buf = 0;
    for (; tile < ntiles; tile += gridDim.x) {
        int nxt = tile + gridDim.x;
        float* Xcur = buf ? Xb1 : Xb0;
        float* Xnxt = buf ? Xb0 : Xb1;
        if (nxt < ntiles) {
            stage(nxt, Xnxt);
            asm volatile("cp.async.wait_group 1;" ::: "memory");
        } else {
            asm volatile("cp.async.wait_group 0;" ::: "memory");
        }
        __syncthreads();

        unsigned long long acc0[4], acc1[4];
        const float2* b2 = reinterpret_cast<const float2*>(bias);
        #pragma unroll
        for (int p = 0; p < 4; p++) {
            float2 bp = __ldg(&b2[w * 4 + p]);
            acc0[p] = pack2(bp.x, bp.y);
            acc1[p] = acc0[p];
        }
        #pragma unroll 2
        for (int k = 0; k < CIN; k += 4) {
            float4 x0 = *reinterpret_cast<const float4*>(&Xcur[lane * XS + k]);
            float4 x1 = *reinterpret_cast<const float4*>(&Xcur[(lane + 32) * XS + k]);
            #pragma unroll
            for (int kk = 0; kk < 4; kk++) {
                unsigned long long pa = pack2s((&x0.x)[kk]);
                unsigned long long pb = pack2s((&x1.x)[kk]);
                const ulonglong2* wp =
                    reinterpret_cast<const ulonglong2*>(&Wsm[(k + kk) * 64 + w * 8]);
                ulonglong2 wv0 = wp[0];
                ulonglong2 wv1 = wp[1];
                ffma2(acc0[0], pa, wv0.x); ffma2(acc0[1], pa, wv0.y);
                ffma2(acc0[2], pa, wv1.x); ffma2(acc0[3], pa, wv1.y);
                ffma2(acc1[0], pb, wv0.x); ffma2(acc1[1], pb, wv0.y);
                ffma2(acc1[2], pb, wv1.x); ffma2(acc1[3], pb, wv1.y);
            }
        }
        int row0 = tile * ROWS;
        int g0 = row0 + lane, g1 = row0 + lane + 32;
        if (g0 < n) {
            float a, b;
            __half2 hp[4];
            unpack2(acc0[0], a, b); hp[0] = __floats2half2_rn(a, b);
            unpack2(acc0[1], a, b); hp[1] = __floats2half2_rn(a, b);
            unpack2(acc0[2], a, b); hp[2] = __floats2half2_rn(a, b);
            unpack2(acc0[3], a, b); hp[3] = __floats2half2_rn(a, b);
            *reinterpret_cast<uint4*>(&Yh[(size_t)g0 * 64 + w * 8]) =
                *reinterpret_cast<const uint4*>(hp);
        }
        if (g1 < n) {
            float a, b;
            __half2 hp[4];
            unpack2(acc1[0], a, b); hp[0] = __floats2half2_rn(a, b);
            unpack2(acc1[1], a, b); hp[1] = __floats2half2_rn(a, b);
            unpack2(acc1[2], a, b); hp[2] = __floats2half2_rn(a, b);
            unpack2(acc1[3], a, b); hp[3] = __floats2half2_rn(a, b);
            *reinterpret_cast<uint4*>(&Yh[(size_t)g1 * 64 + w * 8]) =
                *reinterpret_cast<const uint4*>(hp);
        }
        __syncthreads();
        buf ^= 1;
    }
}

// ---------------- prescale bufA by dinv (fp32 math, one fp16 rounding) --------
__global__ void scale_kernel(uint4* __restrict__ Y, const float* __restrict__ dinv,
                             int n) {
    int tid = blockIdx.x * blockDim.x + threadIdx.x;   // one uint4 = 8 halves
    if (tid >= n * 8) return;
    float d = __ldg(&dinv[tid >> 3]);
    uint4 v = Y[tid];
    __half2* h = reinterpret_cast<__half2*>(&v);
    #pragma unroll
    for (int q = 0; q < 4; q++) {
        float2 f = __half22float2(h[q]);
        h[q] = __floats2half2_rn(f.x * d, f.y * d);
    }
    Y[tid] = v;
}

// ---------------- aggregation (prescaled messages, 16-deep MLP) --------------
// out_i = dinv_i * (Y'_i + sum_{p} Y'_{csr[p]}); padding rows point at zero row n.
template <bool LOGSM, bool STATS>
__global__ __launch_bounds__(256)
void agg_kernel(const __half2* __restrict__ Yh,
                const int* __restrict__ rowptr, const int* __restrict__ csr,
                const float* __restrict__ dinv,
                __half2* __restrict__ outh, float2* __restrict__ outf,
                float* __restrict__ stats, int n) {
    int lane = threadIdx.x & 31;
    int wid  = (blockIdx.x * blockDim.x + threadIdx.x) >> 5;
    int nw   = (gridDim.x * blockDim.x) >> 5;
    float s0 = 0.f, q0 = 0.f, s1 = 0.f, q1 = 0.f;

    for (int i = wid; i < n; i += nw) {
        float di = __ldg(&dinv[i]);
        float2 a = __half22float2(__ldg(&Yh[i * 32 + lane]));
        int p = __ldg(&rowptr[i]);
        int e = __ldg(&rowptr[i + 1]);
        for (; p + 16 <= e; p += 16) {
            int4 ja = *reinterpret_cast<const int4*>(&csr[p]);
            int4 jb = *reinterpret_cast<const int4*>(&csr[p + 4]);
            int4 jc = *reinterpret_cast<const int4*>(&csr[p + 8]);
            int4 jd = *reinterpret_cast<const int4*>(&csr[p + 12]);
            float2 v[16];
            v[0]  = __half22float2(__ldg(&Yh[ja.x * 32 + lane]));
            v[1]  = __half22float2(__ldg(&Yh[ja.y * 32 + lane]));
            v[2]  = __half22float2(__ldg(&Yh[ja.z * 32 + lane]));
            v[3]  = __half22float2(__ldg(&Yh[ja.w * 32 + lane]));
            v[4]  = __half22float2(__ldg(&Yh[jb.x * 32 + lane]));
            v[5]  = __half22float2(__ldg(&Yh[jb.y * 32 + lane]));
            v[6]  = __half22float2(__ldg(&Yh[jb.z * 32 + lane]));
            v[7]  = __half22float2(__ldg(&Yh[jb.w * 32 + lane]));
            v[8]  = __half22float2(__ldg(&Yh[jc.x * 32 + lane]));
            v[9]  = __half22float2(__ldg(&Yh[jc.y * 32 + lane]));
            v[10] = __half22float2(__ldg(&Yh[jc.z * 32 + lane]));
            v[11] = __half22float2(__ldg(&Yh[jc.w * 32 + lane]));
            v[12] = __half22float2(__ldg(&Yh[jd.x * 32 + lane]));
            v[13] = __half22float2(__ldg(&Yh[jd.y * 32 + lane]));
            v[14] = __half22float2(__ldg(&Yh[jd.z * 32 + lane]));
            v[15] = __half22float2(__ldg(&Yh[jd.w * 32 + lane]));
            #pragma unroll
            for (int q = 0; q < 16; q++) { a.x += v[q].x; a.y += v[q].y; }
        }
        if (p + 8 <= e) {
            int4 ja = *reinterpret_cast<const int4*>(&csr[p]);
            int4 jb = *reinterpret_cast<const int4*>(&csr[p + 4]);
            float2 v[8];
            v[0] = __half22float2(__ldg(&Yh[ja.x * 32 + lane]));
            v[1] = __half22float2(__ldg(&Yh[ja.y * 32 + lane]));
            v[2] = __half22float2(__ldg(&Yh[ja.z * 32 + lane]));
            v[3] = __half22float2(__ldg(&Yh[ja.w * 32 + lane]));
            v[4] = __half22float2(__ldg(&Yh[jb.x * 32 + lane]));
            v[5] = __half22float2(__ldg(&Yh[jb.y * 32 + lane]));
            v[6] = __half22float2(__ldg(&Yh[jb.z * 32 + lane]));
            v[7] = __half22float2(__ldg(&Yh[jb.w * 32 + lane]));
            #pragma unroll
            for (int q = 0; q < 8; q++) { a.x += v[q].x; a.y += v[q].y; }
            p += 8;
        }
        if (p < e) {
            int4 ja = *reinterpret_cast<const int4*>(&csr[p]);
            float2 v0 = __half22float2(__ldg(&Yh[ja.x * 32 + lane]));
            float2 v1 = __half22float2(__ldg(&Yh[ja.y * 32 + lane]));
            float2 v2 = __half22float2(__ldg(&Yh[ja.z * 32 + lane]));
            float2 v3 = __half22float2(__ldg(&Yh[ja.w * 32 + lane]));
            a.x += (v0.x + v1.x) + (v2.x + v3.x);
            a.y += (v0.y + v1.y) + (v2.y + v3.y);
        }
        a.x *= di;
        a.y *= di;
        if (STATS) {
            s0 += a.x; q0 = fmaf(a.x, a.x, q0);
            s1 += a.y; q1 = fmaf(a.y, a.y, q1);
        }
        if (!LOGSM) {
            outh[i * 32 + lane] = __floats2half2_rn(a.x, a.y);
        } else {
            float m = fmaxf(a.x, a.y);
            #pragma unroll
            for (int o = 16; o > 0; o >>= 1)
                m = fmaxf(m, __shfl_xor_sync(0xFFFFFFFFu, m, o));
            float sum = expf(a.x - m) + expf(a.y - m);
            #pragma unroll
            for (int o = 16; o > 0; o >>= 1)
                sum += __shfl_xor_sync(0xFFFFFFFFu, sum, o);
            float lz = m + logf(sum);
            outf[i * 32 + lane] = make_float2(a.x - lz, a.y - lz);
        }
    }

    if (STATS) {
        __shared__ float4 red[256];
        red[threadIdx.x] = make_float4(s0, q0, s1, q1);
        __syncthreads();
        if (threadIdx.x < 32) {
            float4 r = red[threadIdx.x];
            #pragma unroll
            for (int w = 1; w < 8; w++) {
                float4 o = red[w * 32 + threadIdx.x];
                r.x += o.x; r.y += o.y; r.z += o.z; r.w += o.w;
            }
            atomicAdd(&stats[2 * threadIdx.x],          r.x);
            atomicAdd(&stats[64 + 2 * threadIdx.x],     r.y);
            atomicAdd(&stats[2 * threadIdx.x + 1],      r.z);
            atomicAdd(&stats[64 + 2 * threadIdx.x + 1], r.w);
        }
    }
}

// ---------------- GEMM layers 2/3 (CIN=64, half in, BN+ReLU, dinv prescale) ----
__global__ __launch_bounds__(256)
void gemm2_kernel(const __half* __restrict__ X, const float* __restrict__ W,
                  const float* __restrict__ bias,
                  const float* __restrict__ stat, const float* __restrict__ gam,
                  const float* __restrict__ bet, float invn,
                  const float* __restrict__ dinv,
                  __half* __restrict__ Yh, int n, int ntiles) {
    constexpr int CIN = 64, XS = 68;
    extern __shared__ float sm[];
    float* Wsm = sm;
    float* Xsm = sm + CIN * 64;
    __shared__ float scl[64], shf[64];
    int t = threadIdx.x, w = t >> 5, lane = t & 31;

    if (t < 64) {
        float mean = stat[t] * invn;
        float var  = stat[64 + t] * invn - mean * mean;
        float sc   = rsqrtf(var + 1e-5f) * gam[t];
        scl[t] = sc;
        shf[t] = bet[t] - mean * sc;
    }
    for (int idx = t; idx < CIN * 64; idx += 256) {
        int o = idx & 63, k = idx >> 6;
        Wsm[k * 64 + o] = __ldg(&W[o * CIN + k]);
    }

    for (int tile = blockIdx.x; tile < ntiles; tile += gridDim.x) {
        __syncthreads();
        int row0 = tile * 128;
        for (int idx = t; idx < 128 * (CIN / 4); idx += 256) {
            int r  = idx >> 4;
            int c4 = idx & 15;
            int gr = row0 + r;
            float4 v = make_float4(0.f, 0.f, 0.f, 0.f);
            if (gr < n) {
                const __half2* xh = reinterpret_cast<const __half2*>(
                    X + (size_t)gr * CIN + c4 * 4);
                float2 p0 = __half22float2(xh[0]);
                float2 p1 = __half22float2(xh[1]);
                v = make_float4(p0.x, p0.y, p1.x, p1.y);
            }
            int c = c4 * 4;
            v.x = fmaxf(fmaf(v.x, scl[c],     shf[c]),     0.f);
            v.y = fmaxf(fmaf(v.y, scl[c + 1], shf[c + 1]), 0.f);
            v.z = fmaxf(fmaf(v.z, scl[c + 2], shf[c + 2]), 0.f);
            v.w = fmaxf(fmaf(v.w, scl[c + 3], shf[c + 3]), 0.f);
            *reinterpret_cast<float4*>(&Xsm[r * XS + c4 * 4]) = v;
        }
        __syncthreads();

        unsigned long long acc[4][4];
        const float2* b2 = reinterpret_cast<const float2*>(bias);
        #pragma unroll
        for (int p = 0; p < 4; p++) {
            float2 bp = __ldg(&b2[w * 4 + p]);
            unsigned long long bb = pack2(bp.x, bp.y);
            acc[0][p] = bb; acc[1][p] = bb; acc[2][p] = bb; acc[3][p] = bb;
        }
        #pragma unroll 2
        for (int k = 0; k < CIN; k += 4) {
            float4 xr[4];
            #pragma unroll
            for (int rr = 0; rr < 4; rr++)
                xr[rr] = *reinterpret_cast<const float4*>(&Xsm[(lane + rr * 32) * XS + k]);
            #pragma unroll
            for (int kk = 0; kk < 4; kk++) {
                const ulonglong2* wp =
                    reinterpret_cast<const ulonglong2*>(&Wsm[(k + kk) * 64 + w * 8]);
                ulonglong2 wv0 = wp[0];
                ulonglong2 wv1 = wp[1];
                #pragma unroll
                for (int rr = 0; rr < 4; rr++) {
                    unsigned long long pa = pack2s((&xr[rr].x)[kk]);
                    ffma2(acc[rr][0], pa, wv0.x); ffma2(acc[rr][1], pa, wv0.y);
                    ffma2(acc[rr][2], pa, wv1.x); ffma2(acc[rr][3], pa, wv1.y);
                }
            }
        }
        #pragma unroll
        for (int rr = 0; rr < 4; rr++) {
            int gr = row0 + lane + rr * 32;
            if (gr < n) {
                float di = __ldg(&dinv[gr]);
                float a, b;
                __half2 hp[4];
                unpack2(acc[rr][0], a, b); hp[0] = __floats2half2_rn(a * di, b * di);
                unpack2(acc[rr][1], a, b); hp[1] = __floats2half2_rn(a * di, b * di);
                unpack2(acc[rr][2], a, b); hp[2] = __floats2half2_rn(a * di, b * di);
                unpack2(acc[rr][3], a, b); hp[3] = __floats2half2_rn(a * di, b * di);
                *reinterpret_cast<uint4*>(&Yh[(size_t)gr * 64 + w * 8]) =
                    *reinterpret_cast<const uint4*>(hp);
            }
        }
    }
}

// ---------------- host launcher ----------------
extern "C" void kernel_launch(void* const* d_in, const int* in_sizes, int n_in,
                              void* d_out, int out_size) {
    const float* x   = (const float*)d_in[0];
    const int*   ei  = (const int*)  d_in[1];
    const float* W1  = (const float*)d_in[2];
    const float* b1  = (const float*)d_in[3];
    const float* ga1 = (const float*)d_in[4];
    const float* be1 = (const float*)d_in[5];
    const float* W2  = (const float*)d_in[6];
    const float* b2  = (const float*)d_in[7];
    const float* ga2 = (const float*)d_in[8];
    const float* be2 = (const float*)d_in[9];
    const float* W3  = (const float*)d_in[10];
    const float* b3  = (const float*)d_in[11];
    float* out = (float*)d_out;

    int N = in_sizes[0] / 128;
    int E = in_sizes[1] / 2;
    const int* src = ei;
    const int* dst = ei + E;

    void* p;
    cudaGetSymbolAddress(&p, g_bufA);   __half* bufA  = (__half*)p;
    cudaGetSymbolAddress(&p, g_bufB);   __half* bufB  = (__half*)p;
    cudaGetSymbolAddress(&p, g_csrbuf); int*   csr    = (int*)p;
    cudaGetSymbolAddress(&p, g_rowptr); int*   rowptr = (int*)p;
    cudaGetSymbolAddress(&p, g_next);   int*   nextp  = (int*)p;
    cudaGetSymbolAddress(&p, g_counts); int*   counts = (int*)p;
    cudaGetSymbolAddress(&p, g_dinv);   float* dinv   = (float*)p;
    cudaGetSymbolAddress(&p, g_stat);   float* stat   = (float*)p;
    cudaGetSymbolAddress(&p, g_bsum);   int*   bsum   = (int*)p;
    cudaGetSymbolAddress(&p, g_boff);   int*   boff   = (int*)p;

    static cudaStream_t sB = nullptr;
    static cudaEvent_t  evF = nullptr, evJ = nullptr;
    if (!sB) {
        cudaStreamCreateWithFlags(&sB, cudaStreamNonBlocking);
        cudaEventCreateWithFlags(&evF, cudaEventDisableTiming);
        cudaEventCreateWithFlags(&evJ, cudaEventDisableTiming);
    }

    const int SMEM1 = (128 * 64 + 2 * 64 * 132) * 4;   // 100352 B
    const int SMEM2 = (64 * 64 + 128 * 68) * 4;        // 51200 B
    cudaFuncSetAttribute(gemm1_kernel,
                         cudaFuncAttributeMaxDynamicSharedMemorySize, SMEM1);
    cudaFuncSetAttribute(gemm2_kernel,
                         cudaFuncAttributeMaxDynamicSharedMemorySize, SMEM2);

    int gridN   = (N + 255) / 256;
    int gridE4  = (E / 4 + 255) / 256;
    int nb      = (N + 1023) / 1024;
    int ntiles1 = (N + 63) / 64;
    int ntiles2 = (N + 127) / 128;
    const int G1   = 296;
    const int G2   = 592;
    const int AGGB = 1184;
    int gridS = (N * 8 + 255) / 256;
    float invn = 1.0f / (float)N;

    const __half2* bufA2 = (const __half2*)bufA;
    __half2* bufB2  = (__half2*)bufB;
    __half2* dummy2 = (__half2*)bufA + (size_t)N * 32;
    float2*  out2   = (float2*)out;

    // ---- fork: CSR build chain on sB overlaps gemm1 (no dinv/csr dep) ----
    cudaEventRecord(evF, 0);
    cudaStreamWaitEvent(sB, evF, 0);

    zero_kernel<<<gridN, 256, 0, sB>>>(counts, stat, dummy2, N);               // 1
    count_kernel<<<gridE4, 256, 0, sB>>>(dst, counts, E);                      // 2
    bsum_kernel<<<nb, 256, 0, sB>>>(counts, bsum, N);                          // 3
    gemm1_kernel<<<G1, 256, SMEM1>>>(x, W1, b1, bufA, N, ntiles1);             // 4 (profiled)
    bscan_kernel<<<1, 128, 0, sB>>>(bsum, boff, rowptr, nb, N);                // 5
    scatter_scan_kernel<<<nb, 256, 0, sB>>>(counts, boff, rowptr, nextp, dinv,
                                            csr, N);                           // 6
    fill_kernel<<<gridE4, 256, 0, sB>>>(src, dst, nextp, csr, E);              // 7
    cudaEventRecord(evJ, sB);
    cudaStreamWaitEvent(0, evJ, 0);

    // prescale layer-1 messages by dinv, then uniform non-RAW aggs
    scale_kernel<<<gridS, 256>>>((uint4*)bufA, dinv, N);                       // 8
    agg_kernel<false, true><<<AGGB, 256>>>(
        bufA2, rowptr, csr, dinv, bufB2, nullptr, stat, N);                    // 9

    // layer 2
    gemm2_kernel<<<G2, 256, SMEM2>>>(bufB, W2, b2, stat, ga1, be1,
                                     invn, dinv, bufA, N, ntiles2);            // 10
    agg_kernel<false, true><<<AGGB, 256>>>(
        bufA2, rowptr, csr, dinv, bufB2, nullptr, stat + 128, N);              // 11

    // layer 3 + log_softmax
    gemm2_kernel<<<G2, 256, SMEM2>>>(bufB, W3, b3, stat + 128, ga2, be2,
                                     invn, dinv, bufA, N, ntiles2);            // 12
    agg_kernel<true, false><<<AGGB, 256>>>(
        bufA2, rowptr, csr, dinv, nullptr, out2, nullptr, N);                  // 13
}